// round 4
// baseline (speedup 1.0000x reference)
#include <cuda_runtime.h>

#define NBATCH 4
#define SEQ    4096
#define HID    2048
#define NE     64
#define NTOK   (NBATCH * SEQ)   // 16384
#define NSPLIT 4
#define KSPAN  (HID / NSPLIT)   // 512

typedef unsigned long long ull;

__device__ float g_wt [HID * NE];             // w^T [k][e]
__device__ float g_wts[HID * NE];             // w^T pair-swapped: [k][e^1]
__device__ float g_part[NSPLIT * NTOK * NE];  // split-K partial logits (16MB)
__device__ float g_ssum[NBATCH * NE];
__device__ int   g_cnt [NBATCH * NE];

__device__ __forceinline__ ull pack2(float lo, float hi) {
    ull r; asm("mov.b64 %0, {%1, %2};" : "=l"(r) : "f"(lo), "f"(hi)); return r;
}
__device__ __forceinline__ void unpack2(ull v, float &lo, float &hi) {
    asm("mov.b64 {%0, %1}, %2;" : "=f"(lo), "=f"(hi) : "l"(v));
}
__device__ __forceinline__ void fma2(ull &d, ull a, ull b) {
    asm("fma.rn.f32x2 %0, %1, %2, %0;" : "+l"(d) : "l"(a), "l"(b));
}

__global__ void zero_acc_kernel() {
    int t = threadIdx.x;
    if (t < NBATCH * NE) { g_ssum[t] = 0.0f; g_cnt[t] = 0; }
}

// transpose w[E][H] -> g_wt[H][E] (and pair-swapped copy g_wts)
__global__ void wt_kernel(const float* __restrict__ w) {
    __shared__ float tile[32][33];
    int bx = blockIdx.x, by = blockIdx.y;          // k-tile 0..63, e-tile 0..1
    int tx = threadIdx.x, ty = threadIdx.y;        // 32 x 8
    #pragma unroll
    for (int i = 0; i < 32; i += 8)
        tile[ty + i][tx] = w[(size_t)(by * 32 + ty + i) * HID + bx * 32 + tx];
    __syncthreads();
    #pragma unroll
    for (int i = 0; i < 32; i += 8) {
        // tile[tx][ty+i] = w[by*32+tx][bx*32+ty+i]  ->  e = by*32+tx, k = bx*32+ty+i
        float v = tile[tx][ty + i];
        int e = by * 32 + tx;
        int k = bx * 32 + ty + i;
        g_wt [(size_t)k * NE + e]       = v;
        g_wts[(size_t)k * NE + (e ^ 1)] = v;
    }
}

// Router GEMM, split-K. grid=1024, block=64. Thread tile: 8 tok x 8 exp.
__global__ __launch_bounds__(64)
void gate_kernel(const float* __restrict__ x) {
    __shared__ __align__(16) float xs[32 * 66];    // [kk][tok], pitch 66

    const int tid    = threadIdx.x;
    const int tile   = blockIdx.x >> 2;
    const int split  = blockIdx.x & 3;
    const int tok0   = tile * 64;
    const int kbase  = split * KSPAN;
    const int m      = tid & 7;
    const int e_base = (tid >> 3) * 8;

    ull acc[4][4], acd[4][4];
    #pragma unroll
    for (int q = 0; q < 4; q++)
        #pragma unroll
        for (int j = 0; j < 4; j++) { acc[q][j] = 0ull; acd[q][j] = 0ull; }

    for (int t = 0; t < KSPAN / 32; t++) {
        const int kb = kbase + t * 32;
        __syncthreads();
        #pragma unroll
        for (int it = 0; it < 8; it++) {
            int idx = tid + it * 64;
            int tok = idx >> 3, c = idx & 7;
            const float4 v = *(const float4*)(x + (size_t)(tok0 + tok) * HID + kb + c * 4);
            xs[(c * 4 + 0) * 66 + tok] = v.x;
            xs[(c * 4 + 1) * 66 + tok] = v.y;
            xs[(c * 4 + 2) * 66 + tok] = v.z;
            xs[(c * 4 + 3) * 66 + tok] = v.w;
        }
        __syncthreads();

        #pragma unroll 8
        for (int kk = 0; kk < 32; kk++) {
            const size_t ro = (size_t)(kb + kk) * NE + e_base;
            const ulonglong2 Bn0 = __ldg((const ulonglong2*)(g_wt  + ro));
            const ulonglong2 Bn1 = __ldg((const ulonglong2*)(g_wt  + ro + 4));
            const ulonglong2 Bs0 = __ldg((const ulonglong2*)(g_wts + ro));
            const ulonglong2 Bs1 = __ldg((const ulonglong2*)(g_wts + ro + 4));
            #pragma unroll
            for (int q = 0; q < 4; q++) {
                ull A = *(const ull*)(xs + kk * 66 + q * 16 + m * 2);
                fma2(acc[q][0], A, Bn0.x); fma2(acd[q][0], A, Bs0.x);
                fma2(acc[q][1], A, Bn0.y); fma2(acd[q][1], A, Bs0.y);
                fma2(acc[q][2], A, Bn1.x); fma2(acd[q][2], A, Bs1.x);
                fma2(acc[q][3], A, Bn1.y); fma2(acd[q][3], A, Bs1.y);
            }
        }
    }

    // acc[q][j]=(L[t0][e0], L[t1][e0+1]); acd[q][j]=(L[t0][e0+1], L[t1][e0])
    float* P = g_part + (size_t)split * NTOK * NE;
    #pragma unroll
    for (int q = 0; q < 4; q++) {
        const int t0 = tok0 + q * 16 + m * 2;
        #pragma unroll
        for (int j = 0; j < 4; j++) {
            float alo, ahi, dlo, dhi;
            unpack2(acc[q][j], alo, ahi);
            unpack2(acd[q][j], dlo, dhi);
            const int e0 = e_base + 2 * j;
            *(ull*)(P + (size_t)t0 * NE + e0)       = pack2(alo, dlo);
            *(ull*)(P + (size_t)(t0 + 1) * NE + e0) = pack2(dhi, ahi);
        }
    }
}

// Fused epilogue: sum partials -> softmax -> top2 -> outputs + aux accum.
__global__ __launch_bounds__(256)
void epi_kernel(float* __restrict__ out) {
    __shared__ float ssum_s[NE];
    __shared__ int   cnt_s[NE];
    const int tid = threadIdx.x, warp = tid >> 5, lane = tid & 31;
    if (tid < NE) { ssum_s[tid] = 0.0f; cnt_s[tid] = 0; }
    __syncthreads();

    const int t = blockIdx.x * 8 + warp;

    float L0 = 0.0f, L1 = 0.0f;
    #pragma unroll
    for (int s = 0; s < NSPLIT; s++) {
        float a, b;
        unpack2(*(const ull*)(g_part + ((size_t)s * NTOK + t) * NE + 2 * lane), a, b);
        L0 += a; L1 += b;
    }

    float mx = fmaxf(L0, L1);
    #pragma unroll
    for (int o = 16; o; o >>= 1) mx = fmaxf(mx, __shfl_xor_sync(0xffffffffu, mx, o));
    float e0 = expf(L0 - mx), e1 = expf(L1 - mx);
    float z = e0 + e1;
    #pragma unroll
    for (int o = 16; o; o >>= 1) z += __shfl_xor_sync(0xffffffffu, z, o);
    float p0 = e0 / z, p1 = e1 / z;

    atomicAdd(&ssum_s[2 * lane],     p0);
    atomicAdd(&ssum_s[2 * lane + 1], p1);

    // lane-local top2 (tie -> lower index), then butterfly merge
    float tv1, tv2; int ti1, ti2;
    if (p0 >= p1) { tv1 = p0; ti1 = 2 * lane;     tv2 = p1; ti2 = 2 * lane + 1; }
    else          { tv1 = p1; ti1 = 2 * lane + 1; tv2 = p0; ti2 = 2 * lane;     }
    #pragma unroll
    for (int o = 16; o; o >>= 1) {
        float ov1 = __shfl_xor_sync(0xffffffffu, tv1, o);
        int   oi1 = __shfl_xor_sync(0xffffffffu, ti1, o);
        float ov2 = __shfl_xor_sync(0xffffffffu, tv2, o);
        int   oi2 = __shfl_xor_sync(0xffffffffu, ti2, o);
        bool obeats = (ov1 > tv1) || (ov1 == tv1 && oi1 < ti1);
        if (obeats) {
            float nv2; int ni2;
            bool mine2 = (tv1 > ov2) || (tv1 == ov2 && ti1 < oi2);
            if (mine2) { nv2 = tv1; ni2 = ti1; } else { nv2 = ov2; ni2 = oi2; }
            tv1 = ov1; ti1 = oi1; tv2 = nv2; ti2 = ni2;
        } else {
            bool beats2 = (ov1 > tv2) || (ov1 == tv2 && oi1 < ti2);
            if (beats2) { tv2 = ov1; ti2 = oi1; }
        }
    }

    if (lane == 0) {
        out[2 * t + 0] = (float)ti1;
        out[2 * t + 1] = (float)ti2;
        float zz = tv1 + tv2 + 1e-20f;
        out[2 * NTOK + 2 * t + 0] = tv1 / zz;
        out[2 * NTOK + 2 * t + 1] = tv2 / zz;
        atomicAdd(&cnt_s[ti1], 1);
        atomicAdd(&cnt_s[ti2], 1);
    }
    __syncthreads();

    const int b = (blockIdx.x * 8) >> 12;   // batch (4096 tokens each)
    if (tid < NE) {
        atomicAdd(&g_ssum[b * NE + tid], ssum_s[tid]);
        atomicAdd(&g_cnt [b * NE + tid], cnt_s[tid]);
    }
}

__global__ void aux_kernel(float* __restrict__ out) {
    int t = threadIdx.x;  // 256 = NBATCH*NE
    float v = ((float)g_cnt[t] * ((float)NE / (float)(SEQ * 2))) *
              (g_ssum[t] / (float)SEQ);
    #pragma unroll
    for (int o = 16; o; o >>= 1) v += __shfl_xor_sync(0xffffffffu, v, o);
    __shared__ float wsum[8];
    if ((t & 31) == 0) wsum[t >> 5] = v;
    __syncthreads();
    if (t < 8) {
        float s = wsum[t];
        #pragma unroll
        for (int o = 4; o; o >>= 1) s += __shfl_xor_sync(0xffu, s, o);
        if (t == 0) out[4 * NTOK] = 0.01f * s / (float)NBATCH;
    }
}

extern "C" void kernel_launch(void* const* d_in, const int* in_sizes, int n_in,
                              void* d_out, int out_size) {
    const float* x = (const float*)d_in[0];
    const float* w = (const float*)d_in[1];
    float* out = (float*)d_out;

    zero_acc_kernel<<<1, 256>>>();
    wt_kernel<<<dim3(64, 2), dim3(32, 8)>>>(w);
    gate_kernel<<<NTOK / 64 * NSPLIT, 64>>>(x);
    epi_kernel<<<NTOK / 8, 256>>>(out);
    aux_kernel<<<1, 256>>>(out);
}

// round 5
// speedup vs baseline: 2.3285x; 2.3285x over previous
#include <cuda_runtime.h>

#define NBATCH 4
#define SEQ    4096
#define HID    2048
#define NE     64
#define NTOK   (NBATCH * SEQ)   // 16384
#define NSPLIT 4
#define KSPAN  (HID / NSPLIT)   // 512

typedef unsigned long long ull;

__device__ float g_wt [HID * NE];             // w^T [k][e]
__device__ float g_part[NSPLIT * NTOK * NE];  // split-K partial logits (16MB)
__device__ float g_ssum[NBATCH * NE];
__device__ int   g_cnt [NBATCH * NE];

__device__ __forceinline__ ull pack2(float lo, float hi) {
    ull r; asm("mov.b64 %0, {%1, %2};" : "=l"(r) : "f"(lo), "f"(hi)); return r;
}
__device__ __forceinline__ void unpack2(ull v, float &lo, float &hi) {
    asm("mov.b64 {%0, %1}, %2;" : "=f"(lo), "=f"(hi) : "l"(v));
}
__device__ __forceinline__ void fma2(ull &d, ull a, ull b) {
    asm("fma.rn.f32x2 %0, %1, %2, %0;" : "+l"(d) : "l"(a), "l"(b));
}

// transpose w[E][H] -> g_wt[H][E]; block(0,0) also zeroes aux accumulators
__global__ void wt_kernel(const float* __restrict__ w) {
    __shared__ float tile[32][33];
    int bx = blockIdx.x, by = blockIdx.y;          // k-tile 0..63, e-tile 0..1
    int tx = threadIdx.x, ty = threadIdx.y;        // 32 x 8
    int t = ty * 32 + tx;
    if (bx == 0 && by == 0 && t < NBATCH * NE) { g_ssum[t] = 0.0f; g_cnt[t] = 0; }
    #pragma unroll
    for (int i = 0; i < 32; i += 8)
        tile[ty + i][tx] = w[(size_t)(by * 32 + ty + i) * HID + bx * 32 + tx];
    __syncthreads();
    #pragma unroll
    for (int i = 0; i < 32; i += 8) {
        // tile[tx][ty+i] = w[by*32+tx][bx*32+ty+i] -> e = by*32+tx, k = bx*32+ty+i
        int e = by * 32 + tx;
        int k = bx * 32 + ty + i;
        g_wt[(size_t)k * NE + e] = tile[tx][ty + i];
    }
}

// Router GEMM, split-K=4. grid=1024, block=64. Thread tile: 8 tok x 8 exp.
// All inner-loop operands from smem as natural 64/128-bit pairs.
__global__ __launch_bounds__(64)
void gate_kernel(const float* __restrict__ x) {
    __shared__ __align__(16) float xs [32 * 66];   // [kk][tok], pitch 66
    __shared__ __align__(16) float wsn[32 * 64];   // [kk][e]
    __shared__ __align__(16) float wss[32 * 64];   // [kk][e^1]

    const int tid    = threadIdx.x;
    const int tile   = blockIdx.x >> 2;
    const int split  = blockIdx.x & 3;
    const int tok0   = tile * 64;
    const int kbase  = split * KSPAN;
    const int m      = tid & 7;
    const int e_base = (tid >> 3) * 8;

    ull acc[4][4], acd[4][4];
    #pragma unroll
    for (int q = 0; q < 4; q++)
        #pragma unroll
        for (int j = 0; j < 4; j++) { acc[q][j] = 0ull; acd[q][j] = 0ull; }

    for (int t = 0; t < KSPAN / 32; t++) {
        const int kb = kbase + t * 32;
        __syncthreads();
        // stage x transposed: 64 tok x 32 k
        #pragma unroll
        for (int it = 0; it < 8; it++) {
            int idx = tid + it * 64;
            int tok = idx >> 3, c = idx & 7;
            const float4 v = *(const float4*)(x + (size_t)(tok0 + tok) * HID + kb + c * 4);
            xs[(c * 4 + 0) * 66 + tok] = v.x;
            xs[(c * 4 + 1) * 66 + tok] = v.y;
            xs[(c * 4 + 2) * 66 + tok] = v.z;
            xs[(c * 4 + 3) * 66 + tok] = v.w;
        }
        // stage w rows (straight copy + pair-swapped copy), conflict-free
        #pragma unroll
        for (int it = 0; it < 8; it++) {
            int idx = tid + it * 64;         // 0..511
            int row = idx >> 4, c4 = idx & 15;
            const float4 v = *(const float4*)(g_wt + (size_t)(kb + row) * NE + c4 * 4);
            *(float4*)(wsn + row * 64 + c4 * 4) = v;
            *(float4*)(wss + row * 64 + c4 * 4) = make_float4(v.y, v.x, v.w, v.z);
        }
        __syncthreads();

        #pragma unroll 4
        for (int kk = 0; kk < 32; kk++) {
            const float* wr = wsn + kk * 64 + e_base;
            const float* sr = wss + kk * 64 + e_base;
            const ulonglong2 Bn01 = *(const ulonglong2*)(wr);
            const ulonglong2 Bn23 = *(const ulonglong2*)(wr + 4);
            const ulonglong2 Bs01 = *(const ulonglong2*)(sr);
            const ulonglong2 Bs23 = *(const ulonglong2*)(sr + 4);
            #pragma unroll
            for (int q = 0; q < 4; q++) {
                ull A = *(const ull*)(xs + kk * 66 + q * 16 + m * 2);
                fma2(acc[q][0], A, Bn01.x); fma2(acd[q][0], A, Bs01.x);
                fma2(acc[q][1], A, Bn01.y); fma2(acd[q][1], A, Bs01.y);
                fma2(acc[q][2], A, Bn23.x); fma2(acd[q][2], A, Bs23.x);
                fma2(acc[q][3], A, Bn23.y); fma2(acd[q][3], A, Bs23.y);
            }
        }
    }

    // acc[q][j]=(L[t0][e0], L[t1][e0+1]); acd[q][j]=(L[t0][e0+1], L[t1][e0])
    float* P = g_part + (size_t)split * NTOK * NE;
    #pragma unroll
    for (int q = 0; q < 4; q++) {
        const int t0 = tok0 + q * 16 + m * 2;
        #pragma unroll
        for (int j = 0; j < 4; j++) {
            float alo, ahi, dlo, dhi;
            unpack2(acc[q][j], alo, ahi);
            unpack2(acd[q][j], dlo, dhi);
            const int e0 = e_base + 2 * j;
            *(ull*)(P + (size_t)t0 * NE + e0)       = pack2(alo, dlo);
            *(ull*)(P + (size_t)(t0 + 1) * NE + e0) = pack2(dhi, ahi);
        }
    }
}

// Fused epilogue: sum partials -> softmax -> top2 -> outputs + aux accum.
__global__ __launch_bounds__(256)
void epi_kernel(float* __restrict__ out) {
    __shared__ float ssum_s[NE];
    __shared__ int   cnt_s[NE];
    const int tid = threadIdx.x, warp = tid >> 5, lane = tid & 31;
    if (tid < NE) { ssum_s[tid] = 0.0f; cnt_s[tid] = 0; }
    __syncthreads();

    const int t = blockIdx.x * 8 + warp;

    float L0 = 0.0f, L1 = 0.0f;
    #pragma unroll
    for (int s = 0; s < NSPLIT; s++) {
        float a, b;
        unpack2(*(const ull*)(g_part + ((size_t)s * NTOK + t) * NE + 2 * lane), a, b);
        L0 += a; L1 += b;
    }

    float mx = fmaxf(L0, L1);
    #pragma unroll
    for (int o = 16; o; o >>= 1) mx = fmaxf(mx, __shfl_xor_sync(0xffffffffu, mx, o));
    float e0 = expf(L0 - mx), e1 = expf(L1 - mx);
    float z = e0 + e1;
    #pragma unroll
    for (int o = 16; o; o >>= 1) z += __shfl_xor_sync(0xffffffffu, z, o);
    float p0 = e0 / z, p1 = e1 / z;

    atomicAdd(&ssum_s[2 * lane],     p0);
    atomicAdd(&ssum_s[2 * lane + 1], p1);

    float tv1, tv2; int ti1, ti2;
    if (p0 >= p1) { tv1 = p0; ti1 = 2 * lane;     tv2 = p1; ti2 = 2 * lane + 1; }
    else          { tv1 = p1; ti1 = 2 * lane + 1; tv2 = p0; ti2 = 2 * lane;     }
    #pragma unroll
    for (int o = 16; o; o >>= 1) {
        float ov1 = __shfl_xor_sync(0xffffffffu, tv1, o);
        int   oi1 = __shfl_xor_sync(0xffffffffu, ti1, o);
        float ov2 = __shfl_xor_sync(0xffffffffu, tv2, o);
        int   oi2 = __shfl_xor_sync(0xffffffffu, ti2, o);
        bool obeats = (ov1 > tv1) || (ov1 == tv1 && oi1 < ti1);
        if (obeats) {
            float nv2; int ni2;
            bool mine2 = (tv1 > ov2) || (tv1 == ov2 && ti1 < oi2);
            if (mine2) { nv2 = tv1; ni2 = ti1; } else { nv2 = ov2; ni2 = oi2; }
            tv1 = ov1; ti1 = oi1; tv2 = nv2; ti2 = ni2;
        } else {
            bool beats2 = (ov1 > tv2) || (ov1 == tv2 && oi1 < ti2);
            if (beats2) { tv2 = ov1; ti2 = oi1; }
        }
    }

    if (lane == 0) {
        out[2 * t + 0] = (float)ti1;
        out[2 * t + 1] = (float)ti2;
        float zz = tv1 + tv2 + 1e-20f;
        out[2 * NTOK + 2 * t + 0] = tv1 / zz;
        out[2 * NTOK + 2 * t + 1] = tv2 / zz;
        atomicAdd(&cnt_s[ti1], 1);
        atomicAdd(&cnt_s[ti2], 1);
    }
    __syncthreads();

    const int b = (blockIdx.x * 8) >> 12;   // /4096 tokens per batch
    if (tid < NE) {
        atomicAdd(&g_ssum[b * NE + tid], ssum_s[tid]);
        atomicAdd(&g_cnt [b * NE + tid], cnt_s[tid]);
    }
}

__global__ void aux_kernel(float* __restrict__ out) {
    int t = threadIdx.x;  // 256 = NBATCH*NE
    float v = ((float)g_cnt[t] * ((float)NE / (float)(SEQ * 2))) *
              (g_ssum[t] / (float)SEQ);
    #pragma unroll
    for (int o = 16; o; o >>= 1) v += __shfl_xor_sync(0xffffffffu, v, o);
    __shared__ float wsum[8];
    if ((t & 31) == 0) wsum[t >> 5] = v;
    __syncthreads();
    if (t < 8) {
        float s = wsum[t];
        #pragma unroll
        for (int o = 4; o; o >>= 1) s += __shfl_xor_sync(0xffu, s, o);
        if (t == 0) out[4 * NTOK] = 0.01f * s / (float)NBATCH;
    }
}

extern "C" void kernel_launch(void* const* d_in, const int* in_sizes, int n_in,
                              void* d_out, int out_size) {
    const float* x = (const float*)d_in[0];
    const float* w = (const float*)d_in[1];
    float* out = (float*)d_out;

    wt_kernel<<<dim3(64, 2), dim3(32, 8)>>>(w);
    gate_kernel<<<NTOK / 64 * NSPLIT, 64>>>(x);
    epi_kernel<<<NTOK / 8, 256>>>(out);
    aux_kernel<<<1, 256>>>(out);
}

// round 6
// speedup vs baseline: 2.8424x; 1.2207x over previous
#include <cuda_runtime.h>

#define NBATCH 4
#define SEQ    4096
#define HID    2048
#define NE     64
#define NTOK   (NBATCH * SEQ)   // 16384
#define NSPLIT 4
#define KSPAN  (HID / NSPLIT)   // 512

typedef unsigned long long ull;

__device__ float g_wt [HID * NE];             // w^T [k][e]
__device__ float g_part[NSPLIT * NTOK * NE];  // split-K partial logits (16MB)
__device__ float g_ssum[NBATCH * NE];
__device__ int   g_cnt [NBATCH * NE];

__device__ __forceinline__ ull pack2(float lo, float hi) {
    ull r; asm("mov.b64 %0, {%1, %2};" : "=l"(r) : "f"(lo), "f"(hi)); return r;
}
__device__ __forceinline__ void unpack2(ull v, float &lo, float &hi) {
    asm("mov.b64 {%0, %1}, %2;" : "=f"(lo), "=f"(hi) : "l"(v));
}
__device__ __forceinline__ void fma2(ull &d, ull a, ull b) {
    asm("fma.rn.f32x2 %0, %1, %2, %0;" : "+l"(d) : "l"(a), "l"(b));
}

// transpose w[E][H] -> g_wt[H][E]; block(0,0) also zeroes aux accumulators
__global__ void wt_kernel(const float* __restrict__ w) {
    __shared__ float tile[32][33];
    int bx = blockIdx.x, by = blockIdx.y;          // k-tile 0..63, e-tile 0..1
    int tx = threadIdx.x, ty = threadIdx.y;        // 32 x 8
    int t = ty * 32 + tx;
    if (bx == 0 && by == 0 && t < NBATCH * NE) { g_ssum[t] = 0.0f; g_cnt[t] = 0; }
    #pragma unroll
    for (int i = 0; i < 32; i += 8)
        tile[ty + i][tx] = w[(size_t)(by * 32 + ty + i) * HID + bx * 32 + tx];
    __syncthreads();
    #pragma unroll
    for (int i = 0; i < 32; i += 8) {
        int e = by * 32 + tx;
        int k = bx * 32 + ty + i;
        g_wt[(size_t)k * NE + e] = tile[tx][ty + i];
    }
}

// Router GEMM, split-K=4. grid=1024, block=128 (4 warps -> all 4 SMSPs).
// Tile: 64 tok x 64 exp. Thread tile: 4 tok x 8 exp, pure FFMA2 inner loop.
__global__ __launch_bounds__(128, 6)
void gate_kernel(const float* __restrict__ x) {
    __shared__ __align__(16) float xs [32 * 66];   // [kk][tok], pitch 66
    __shared__ __align__(16) float wsn[32 * 64];   // [kk][e]
    __shared__ __align__(16) float wss[32 * 64];   // [kk][e^1]

    const int tid    = threadIdx.x;
    const int tile   = blockIdx.x >> 2;
    const int split  = blockIdx.x & 3;
    const int tok0   = tile * 64;
    const int kbase  = split * KSPAN;
    const int m      = tid & 15;          // token-pair group 0..15
    const int e_base = (tid >> 4) * 8;    // expert group 0..56

    ull acc[2][4], acd[2][4];
    #pragma unroll
    for (int q = 0; q < 2; q++)
        #pragma unroll
        for (int j = 0; j < 4; j++) { acc[q][j] = 0ull; acd[q][j] = 0ull; }

    for (int t = 0; t < KSPAN / 32; t++) {
        const int kb = kbase + t * 32;
        __syncthreads();
        // stage x transposed: 64 tok x 32 k (4 float4 per thread)
        #pragma unroll
        for (int it = 0; it < 4; it++) {
            int idx = tid + it * 128;
            int tok = idx >> 3, c = idx & 7;
            const float4 v = *(const float4*)(x + (size_t)(tok0 + tok) * HID + kb + c * 4);
            xs[(c * 4 + 0) * 66 + tok] = v.x;
            xs[(c * 4 + 1) * 66 + tok] = v.y;
            xs[(c * 4 + 2) * 66 + tok] = v.z;
            xs[(c * 4 + 3) * 66 + tok] = v.w;
        }
        // stage w rows (straight + pair-swapped), 4 float4 per thread
        #pragma unroll
        for (int it = 0; it < 4; it++) {
            int idx = tid + it * 128;        // 0..511
            int row = idx >> 4, c4 = idx & 15;
            const float4 v = *(const float4*)(g_wt + (size_t)(kb + row) * NE + c4 * 4);
            *(float4*)(wsn + row * 64 + c4 * 4) = v;
            *(float4*)(wss + row * 64 + c4 * 4) = make_float4(v.y, v.x, v.w, v.z);
        }
        __syncthreads();

        #pragma unroll 4
        for (int kk = 0; kk < 32; kk++) {
            const float* wr = wsn + kk * 64 + e_base;
            const float* sr = wss + kk * 64 + e_base;
            const ulonglong2 Bn01 = *(const ulonglong2*)(wr);
            const ulonglong2 Bn23 = *(const ulonglong2*)(wr + 4);
            const ulonglong2 Bs01 = *(const ulonglong2*)(sr);
            const ulonglong2 Bs23 = *(const ulonglong2*)(sr + 4);
            #pragma unroll
            for (int q = 0; q < 2; q++) {
                ull A = *(const ull*)(xs + kk * 66 + q * 32 + m * 2);
                fma2(acc[q][0], A, Bn01.x); fma2(acd[q][0], A, Bs01.x);
                fma2(acc[q][1], A, Bn01.y); fma2(acd[q][1], A, Bs01.y);
                fma2(acc[q][2], A, Bn23.x); fma2(acd[q][2], A, Bs23.x);
                fma2(acc[q][3], A, Bn23.y); fma2(acd[q][3], A, Bs23.y);
            }
        }
    }

    // acc[q][j]=(L[t0][e0], L[t1][e0+1]); acd[q][j]=(L[t0][e0+1], L[t1][e0])
    float* P = g_part + (size_t)split * NTOK * NE;
    #pragma unroll
    for (int q = 0; q < 2; q++) {
        const int t0 = tok0 + q * 32 + m * 2;
        #pragma unroll
        for (int j = 0; j < 4; j++) {
            float alo, ahi, dlo, dhi;
            unpack2(acc[q][j], alo, ahi);
            unpack2(acd[q][j], dlo, dhi);
            const int e0 = e_base + 2 * j;
            *(ull*)(P + (size_t)t0 * NE + e0)       = pack2(alo, dlo);
            *(ull*)(P + (size_t)(t0 + 1) * NE + e0) = pack2(dhi, ahi);
        }
    }
}

// Fused epilogue: sum partials -> softmax -> top2 -> outputs + aux accum.
__global__ __launch_bounds__(256)
void epi_kernel(float* __restrict__ out) {
    __shared__ float ssum_s[NE];
    __shared__ int   cnt_s[NE];
    const int tid = threadIdx.x, warp = tid >> 5, lane = tid & 31;
    if (tid < NE) { ssum_s[tid] = 0.0f; cnt_s[tid] = 0; }
    __syncthreads();

    const int t = blockIdx.x * 8 + warp;

    float L0 = 0.0f, L1 = 0.0f;
    #pragma unroll
    for (int s = 0; s < NSPLIT; s++) {
        float a, b;
        unpack2(*(const ull*)(g_part + ((size_t)s * NTOK + t) * NE + 2 * lane), a, b);
        L0 += a; L1 += b;
    }

    float mx = fmaxf(L0, L1);
    #pragma unroll
    for (int o = 16; o; o >>= 1) mx = fmaxf(mx, __shfl_xor_sync(0xffffffffu, mx, o));
    float e0 = expf(L0 - mx), e1 = expf(L1 - mx);
    float z = e0 + e1;
    #pragma unroll
    for (int o = 16; o; o >>= 1) z += __shfl_xor_sync(0xffffffffu, z, o);
    float p0 = e0 / z, p1 = e1 / z;

    atomicAdd(&ssum_s[2 * lane],     p0);
    atomicAdd(&ssum_s[2 * lane + 1], p1);

    float tv1, tv2; int ti1, ti2;
    if (p0 >= p1) { tv1 = p0; ti1 = 2 * lane;     tv2 = p1; ti2 = 2 * lane + 1; }
    else          { tv1 = p1; ti1 = 2 * lane + 1; tv2 = p0; ti2 = 2 * lane;     }
    #pragma unroll
    for (int o = 16; o; o >>= 1) {
        float ov1 = __shfl_xor_sync(0xffffffffu, tv1, o);
        int   oi1 = __shfl_xor_sync(0xffffffffu, ti1, o);
        float ov2 = __shfl_xor_sync(0xffffffffu, tv2, o);
        int   oi2 = __shfl_xor_sync(0xffffffffu, ti2, o);
        bool obeats = (ov1 > tv1) || (ov1 == tv1 && oi1 < ti1);
        if (obeats) {
            float nv2; int ni2;
            bool mine2 = (tv1 > ov2) || (tv1 == ov2 && ti1 < oi2);
            if (mine2) { nv2 = tv1; ni2 = ti1; } else { nv2 = ov2; ni2 = oi2; }
            tv1 = ov1; ti1 = oi1; tv2 = nv2; ti2 = ni2;
        } else {
            bool beats2 = (ov1 > tv2) || (ov1 == tv2 && oi1 < ti2);
            if (beats2) { tv2 = ov1; ti2 = oi1; }
        }
    }

    if (lane == 0) {
        out[2 * t + 0] = (float)ti1;
        out[2 * t + 1] = (float)ti2;
        float zz = tv1 + tv2 + 1e-20f;
        out[2 * NTOK + 2 * t + 0] = tv1 / zz;
        out[2 * NTOK + 2 * t + 1] = tv2 / zz;
        atomicAdd(&cnt_s[ti1], 1);
        atomicAdd(&cnt_s[ti2], 1);
    }
    __syncthreads();

    const int b = (blockIdx.x * 8) >> 12;   // /4096 tokens per batch
    if (tid < NE) {
        atomicAdd(&g_ssum[b * NE + tid], ssum_s[tid]);
        atomicAdd(&g_cnt [b * NE + tid], cnt_s[tid]);
    }
}

__global__ void aux_kernel(float* __restrict__ out) {
    int t = threadIdx.x;  // 256 = NBATCH*NE
    float v = ((float)g_cnt[t] * ((float)NE / (float)(SEQ * 2))) *
              (g_ssum[t] / (float)SEQ);
    #pragma unroll
    for (int o = 16; o; o >>= 1) v += __shfl_xor_sync(0xffffffffu, v, o);
    __shared__ float wsum[8];
    if ((t & 31) == 0) wsum[t >> 5] = v;
    __syncthreads();
    if (t < 8) {
        float s = wsum[t];
        #pragma unroll
        for (int o = 4; o; o >>= 1) s += __shfl_xor_sync(0xffu, s, o);
        if (t == 0) out[4 * NTOK] = 0.01f * s / (float)NBATCH;
    }
}

extern "C" void kernel_launch(void* const* d_in, const int* in_sizes, int n_in,
                              void* d_out, int out_size) {
    const float* x = (const float*)d_in[0];
    const float* w = (const float*)d_in[1];
    float* out = (float*)d_out;

    wt_kernel<<<dim3(64, 2), dim3(32, 8)>>>(w);
    gate_kernel<<<NTOK / 64 * NSPLIT, 128>>>(x);
    epi_kernel<<<NTOK / 8, 256>>>(out);
    aux_kernel<<<1, 256>>>(out);
}

// round 7
// speedup vs baseline: 3.0541x; 1.0745x over previous
#include <cuda_runtime.h>

#define NBATCH 4
#define SEQ    4096
#define HID    2048
#define NE     64
#define NTOK   (NBATCH * SEQ)   // 16384
#define NSPLIT 8
#define KSPAN  (HID / NSPLIT)   // 256
#define TTILE  128              // tokens per block

typedef unsigned long long ull;

__device__ float g_wt [HID * NE];             // w^T [k][e]
__device__ float g_wts[HID * NE];             // w^T pair-swapped [k][e^1]
__device__ float g_part[NSPLIT * NTOK * NE];  // split-K partial logits (32MB)
__device__ float g_ssum[NBATCH * NE];
__device__ int   g_cnt [NBATCH * NE];

__device__ __forceinline__ ull pack2(float lo, float hi) {
    ull r; asm("mov.b64 %0, {%1, %2};" : "=l"(r) : "f"(lo), "f"(hi)); return r;
}
__device__ __forceinline__ void unpack2(ull v, float &lo, float &hi) {
    asm("mov.b64 {%0, %1}, %2;" : "=f"(lo), "=f"(hi) : "l"(v));
}
__device__ __forceinline__ void fma2(ull &d, ull a, ull b) {
    asm("fma.rn.f32x2 %0, %1, %2, %0;" : "+l"(d) : "l"(a), "l"(b));
}

// transpose w[E][H] -> g_wt[H][E] + pair-swapped g_wts; block(0,0) zeroes aux
__global__ void wt_kernel(const float* __restrict__ w) {
    __shared__ float tile[32][33];
    int bx = blockIdx.x, by = blockIdx.y;          // k-tile 0..63, e-tile 0..1
    int tx = threadIdx.x, ty = threadIdx.y;        // 32 x 8
    int t = ty * 32 + tx;
    if (bx == 0 && by == 0 && t < NBATCH * NE) { g_ssum[t] = 0.0f; g_cnt[t] = 0; }
    #pragma unroll
    for (int i = 0; i < 32; i += 8)
        tile[ty + i][tx] = w[(size_t)(by * 32 + ty + i) * HID + bx * 32 + tx];
    __syncthreads();
    #pragma unroll
    for (int i = 0; i < 32; i += 8) {
        // tile[tx][ty+i] = w[by*32+tx][bx*32+ty+i] -> e = by*32+tx, k = bx*32+ty+i
        float v = tile[tx][ty + i];
        int e = by * 32 + tx;
        int k = bx * 32 + ty + i;
        g_wt [(size_t)k * NE + e]       = v;
        g_wts[(size_t)k * NE + (e ^ 1)] = v;
    }
}

// Router GEMM, split-K=8. grid=1024, block=128 (4 warps -> all 4 SMSPs).
// Block tile: 128 tok x 64 exp. Thread tile: 8 tok x 8 exp, pure FFMA2.
__global__ __launch_bounds__(128, 4)
void gate_kernel(const float* __restrict__ x) {
    __shared__ __align__(16) float xs [32 * 130];  // [kk][tok], pitch 130
    __shared__ __align__(16) float wsn[32 * 64];   // [kk][e]
    __shared__ __align__(16) float wss[32 * 64];   // [kk][e^1]

    const int tid    = threadIdx.x;
    const int tile   = blockIdx.x >> 3;
    const int split  = blockIdx.x & 7;
    const int tok0   = tile * TTILE;
    const int kbase  = split * KSPAN;
    const int m      = tid & 15;          // token-pair group 0..15
    const int e_base = (tid >> 4) * 8;    // expert group 0..56

    ull acc[4][4], acd[4][4];
    #pragma unroll
    for (int q = 0; q < 4; q++)
        #pragma unroll
        for (int j = 0; j < 4; j++) { acc[q][j] = 0ull; acd[q][j] = 0ull; }

    for (int t = 0; t < KSPAN / 32; t++) {
        const int kb = kbase + t * 32;
        __syncthreads();
        // stage x transposed: 128 tok x 32 k (8 float4 per thread)
        #pragma unroll
        for (int it = 0; it < 8; it++) {
            int idx = tid + it * 128;
            int tok = idx >> 3, c = idx & 7;
            const float4 v = *(const float4*)(x + (size_t)(tok0 + tok) * HID + kb + c * 4);
            xs[(c * 4 + 0) * 130 + tok] = v.x;
            xs[(c * 4 + 1) * 130 + tok] = v.y;
            xs[(c * 4 + 2) * 130 + tok] = v.z;
            xs[(c * 4 + 3) * 130 + tok] = v.w;
        }
        // stage w rows: straight copies of both precomputed arrays
        #pragma unroll
        for (int it = 0; it < 4; it++) {
            int idx = tid + it * 128;        // 0..511
            int row = idx >> 4, c4 = idx & 15;
            *(float4*)(wsn + row * 64 + c4 * 4) =
                *(const float4*)(g_wt  + (size_t)(kb + row) * NE + c4 * 4);
            *(float4*)(wss + row * 64 + c4 * 4) =
                *(const float4*)(g_wts + (size_t)(kb + row) * NE + c4 * 4);
        }
        __syncthreads();

        #pragma unroll 4
        for (int kk = 0; kk < 32; kk++) {
            const float* wr = wsn + kk * 64 + e_base;
            const float* sr = wss + kk * 64 + e_base;
            const ulonglong2 Bn01 = *(const ulonglong2*)(wr);
            const ulonglong2 Bn23 = *(const ulonglong2*)(wr + 4);
            const ulonglong2 Bs01 = *(const ulonglong2*)(sr);
            const ulonglong2 Bs23 = *(const ulonglong2*)(sr + 4);
            #pragma unroll
            for (int q = 0; q < 4; q++) {
                ull A = *(const ull*)(xs + kk * 130 + q * 32 + m * 2);
                fma2(acc[q][0], A, Bn01.x); fma2(acd[q][0], A, Bs01.x);
                fma2(acc[q][1], A, Bn01.y); fma2(acd[q][1], A, Bs01.y);
                fma2(acc[q][2], A, Bn23.x); fma2(acd[q][2], A, Bs23.x);
                fma2(acc[q][3], A, Bn23.y); fma2(acd[q][3], A, Bs23.y);
            }
        }
    }

    // acc[q][j]=(L[t0][e0], L[t1][e0+1]); acd[q][j]=(L[t0][e0+1], L[t1][e0])
    float* P = g_part + (size_t)split * NTOK * NE;
    #pragma unroll
    for (int q = 0; q < 4; q++) {
        const int t0 = tok0 + q * 32 + m * 2;
        #pragma unroll
        for (int j = 0; j < 4; j++) {
            float alo, ahi, dlo, dhi;
            unpack2(acc[q][j], alo, ahi);
            unpack2(acd[q][j], dlo, dhi);
            const int e0 = e_base + 2 * j;
            *(ull*)(P + (size_t)t0 * NE + e0)       = pack2(alo, dlo);
            *(ull*)(P + (size_t)(t0 + 1) * NE + e0) = pack2(dhi, ahi);
        }
    }
}

// Fused epilogue: sum partials -> softmax -> top2 -> outputs + aux accum.
__global__ __launch_bounds__(256)
void epi_kernel(float* __restrict__ out) {
    __shared__ float ssum_s[NE];
    __shared__ int   cnt_s[NE];
    const int tid = threadIdx.x, warp = tid >> 5, lane = tid & 31;
    if (tid < NE) { ssum_s[tid] = 0.0f; cnt_s[tid] = 0; }
    __syncthreads();

    const int t = blockIdx.x * 8 + warp;

    float L0 = 0.0f, L1 = 0.0f;
    #pragma unroll
    for (int s = 0; s < NSPLIT; s++) {
        float a, b;
        unpack2(*(const ull*)(g_part + ((size_t)s * NTOK + t) * NE + 2 * lane), a, b);
        L0 += a; L1 += b;
    }

    float mx = fmaxf(L0, L1);
    #pragma unroll
    for (int o = 16; o; o >>= 1) mx = fmaxf(mx, __shfl_xor_sync(0xffffffffu, mx, o));
    float e0 = expf(L0 - mx), e1 = expf(L1 - mx);
    float z = e0 + e1;
    #pragma unroll
    for (int o = 16; o; o >>= 1) z += __shfl_xor_sync(0xffffffffu, z, o);
    float p0 = e0 / z, p1 = e1 / z;

    atomicAdd(&ssum_s[2 * lane],     p0);
    atomicAdd(&ssum_s[2 * lane + 1], p1);

    float tv1, tv2; int ti1, ti2;
    if (p0 >= p1) { tv1 = p0; ti1 = 2 * lane;     tv2 = p1; ti2 = 2 * lane + 1; }
    else          { tv1 = p1; ti1 = 2 * lane + 1; tv2 = p0; ti2 = 2 * lane;     }
    #pragma unroll
    for (int o = 16; o; o >>= 1) {
        float ov1 = __shfl_xor_sync(0xffffffffu, tv1, o);
        int   oi1 = __shfl_xor_sync(0xffffffffu, ti1, o);
        float ov2 = __shfl_xor_sync(0xffffffffu, tv2, o);
        int   oi2 = __shfl_xor_sync(0xffffffffu, ti2, o);
        bool obeats = (ov1 > tv1) || (ov1 == tv1 && oi1 < ti1);
        if (obeats) {
            float nv2; int ni2;
            bool mine2 = (tv1 > ov2) || (tv1 == ov2 && ti1 < oi2);
            if (mine2) { nv2 = tv1; ni2 = ti1; } else { nv2 = ov2; ni2 = oi2; }
            tv1 = ov1; ti1 = oi1; tv2 = nv2; ti2 = ni2;
        } else {
            bool beats2 = (ov1 > tv2) || (ov1 == tv2 && oi1 < ti2);
            if (beats2) { tv2 = ov1; ti2 = oi1; }
        }
    }

    if (lane == 0) {
        out[2 * t + 0] = (float)ti1;
        out[2 * t + 1] = (float)ti2;
        float zz = tv1 + tv2 + 1e-20f;
        out[2 * NTOK + 2 * t + 0] = tv1 / zz;
        out[2 * NTOK + 2 * t + 1] = tv2 / zz;
        atomicAdd(&cnt_s[ti1], 1);
        atomicAdd(&cnt_s[ti2], 1);
    }
    __syncthreads();

    const int b = (blockIdx.x * 8) >> 12;   // /4096 tokens per batch
    if (tid < NE) {
        atomicAdd(&g_ssum[b * NE + tid], ssum_s[tid]);
        atomicAdd(&g_cnt [b * NE + tid], cnt_s[tid]);
    }
}

__global__ void aux_kernel(float* __restrict__ out) {
    int t = threadIdx.x;  // 256 = NBATCH*NE
    float v = ((float)g_cnt[t] * ((float)NE / (float)(SEQ * 2))) *
              (g_ssum[t] / (float)SEQ);
    #pragma unroll
    for (int o = 16; o; o >>= 1) v += __shfl_xor_sync(0xffffffffu, v, o);
    __shared__ float wsum[8];
    if ((t & 31) == 0) wsum[t >> 5] = v;
    __syncthreads();
    if (t < 8) {
        float s = wsum[t];
        #pragma unroll
        for (int o = 4; o; o >>= 1) s += __shfl_xor_sync(0xffu, s, o);
        if (t == 0) out[4 * NTOK] = 0.01f * s / (float)NBATCH;
    }
}

extern "C" void kernel_launch(void* const* d_in, const int* in_sizes, int n_in,
                              void* d_out, int out_size) {
    const float* x = (const float*)d_in[0];
    const float* w = (const float*)d_in[1];
    float* out = (float*)d_out;

    wt_kernel<<<dim3(64, 2), dim3(32, 8)>>>(w);
    gate_kernel<<<NTOK / TTILE * NSPLIT, 128>>>(x);
    epi_kernel<<<NTOK / 8, 256>>>(out);
    aux_kernel<<<1, 256>>>(out);
}